// round 8
// baseline (speedup 1.0000x reference)
#include <cuda_runtime.h>
#include <cuda_bf16.h>
#include <cstdint>

// VQVAE nearest-codebook: bf16 mma.sync fast scores (register-cached) +
// warp-parallel exact fp32 rescore. z:[131072,64] f32, cb:[512,64] f32.
// out = (gather, gather).

#define Dm 64
#define Kc 512
#define ROWS_CTA 128
#define THREADS 512
#define MARGIN 2e-3f
#define SSLACK 1.2e-3f
#define QCAP 64

__device__ float g_ee[Kc];            // exact sequential ||e_j||^2
__device__ int g_eemax_i = 0;         // max ee (float bits); atomicMax idempotent
__device__ unsigned g_cbw[Kc * 32];   // codebook rows, bf16x2 words, B-pair permuted

// ---- smem layout (bytes) ----
#define SM_ZBW  0                      // 128 x 36 u32 bf16x2(-2z)                18432
#define SM_BSW  18432                  // 512 x 40 u32 codebook (pitch 40)        81920
#define SM_MREX 100352                 // 2 halves x 128 rows f32 mins             1024
#define SM_ZZS  101376                 // 128 f32 exact zz                          512
#define SM_MINR 101888                 // 128 u64 (score_bits<<32 | j)             1024
#define SM_QCNT 102912                 // 16 i32 (+pad)                             128
#define SM_QUE  103040                 // 16 x 64 u32 candidates                   4096
#define SM_TOTAL 107136

__global__ void prep_kernel(const float* __restrict__ cb) {
    int j = blockIdx.x * blockDim.x + threadIdx.x;
    if (j < Kc) {
        const float* e = cb + j * Dm;
        float s = 0.0f;
#pragma unroll
        for (int k = 0; k < Dm; ++k) s = __fadd_rn(s, __fmul_rn(e[k], e[k]));
        g_ee[j] = s;
        atomicMax(&g_eemax_i, __float_as_int(s));   // s >= 0: int order == float order
        // permuted: position p holds word w = (p&~7) + ((p>>1)&3) + 4*(p&1)
#pragma unroll
        for (int p = 0; p < 32; ++p) {
            int w = (p & ~7) + ((p >> 1) & 3) + 4 * (p & 1);
            __nv_bfloat162 b = __float22bfloat162_rn(make_float2(e[2 * w], e[2 * w + 1]));
            g_cbw[j * 32 + p] = *(unsigned*)&b;
        }
    }
}

__device__ __forceinline__ void mma16816(float& c0, float& c1, float& c2, float& c3,
                                         unsigned a0, unsigned a1, unsigned a2, unsigned a3,
                                         unsigned b0, unsigned b1) {
    asm volatile("mma.sync.aligned.m16n8k16.row.col.f32.bf16.bf16.f32 "
                 "{%0,%1,%2,%3},{%4,%5,%6,%7},{%8,%9},{%0,%1,%2,%3};"
                 : "+f"(c0), "+f"(c1), "+f"(c2), "+f"(c3)
                 : "r"(a0), "r"(a1), "r"(a2), "r"(a3), "r"(b0), "r"(b1));
}

// Exact rescore (sequential fp32, reference rounding) + 64-bit atomicMin commit.
// key=(score_bits<<32)|j: scores >= 0 so bit order == value order; ties -> min j.
__device__ __noinline__ void exact_commit(unsigned pk, const float* __restrict__ z,
                                          const float* __restrict__ cb, size_t blockRow,
                                          const float* zzs, unsigned long long* minr) {
    int row = pk & 127;
    int j = pk >> 7;
    const float4* zp = (const float4*)(z + (blockRow + row) * Dm);
    const float4* ep = (const float4*)(cb + (size_t)j * Dm);
    float dot = 0.0f;
#pragma unroll
    for (int i = 0; i < 16; ++i) {
        float4 a = __ldg(zp + i);
        float4 b = __ldg(ep + i);
        dot = __fmaf_rn(a.x, b.x, dot);
        dot = __fmaf_rn(a.y, b.y, dot);
        dot = __fmaf_rn(a.z, b.z, dot);
        dot = __fmaf_rn(a.w, b.w, dot);
    }
    float sx = __fadd_rn(__fadd_rn(zzs[row], g_ee[j]), __fmul_rn(-2.0f, dot));
    unsigned long long key = ((unsigned long long)__float_as_uint(sx) << 32) | (unsigned)j;
    atomicMin(minr + row, key);
}

__global__ void __launch_bounds__(THREADS, 1)
vq_kernel(const float* __restrict__ z, const float* __restrict__ cb,
          float* __restrict__ out, long long half) {
    extern __shared__ char sm[];
    unsigned* zbw = (unsigned*)(sm + SM_ZBW);
    unsigned* bsw = (unsigned*)(sm + SM_BSW);
    float* mrex = (float*)(sm + SM_MREX);
    float* zzs = (float*)(sm + SM_ZZS);
    unsigned long long* minr = (unsigned long long*)(sm + SM_MINR);
    int* qcnt = (int*)(sm + SM_QCNT);
    unsigned* que = (unsigned*)(sm + SM_QUE);

    const int tid = threadIdx.x, lane = tid & 31, wid = tid >> 5;
    const int q = lane & 3, rg = lane >> 2;
    const int gidx = wid & 7, th = wid >> 3;           // row-group, tile-half
    const size_t blockRow = (size_t)blockIdx.x * ROWS_CTA;

    if (tid < 16) qcnt[tid] = 0;

    // ---------------- prolog ----------------
    if (tid < ROWS_CTA) {
        minr[tid] = ~0ull;
        const float4* zr = (const float4*)(z + (blockRow + tid) * Dm);
        float4 v[16];
#pragma unroll
        for (int i = 0; i < 16; ++i) v[i] = zr[i];
        float zz = 0.0f;
#pragma unroll
        for (int i = 0; i < 16; ++i) {
            zz = __fadd_rn(zz, __fmul_rn(v[i].x, v[i].x));
            zz = __fadd_rn(zz, __fmul_rn(v[i].y, v[i].y));
            zz = __fadd_rn(zz, __fmul_rn(v[i].z, v[i].z));
            zz = __fadd_rn(zz, __fmul_rn(v[i].w, v[i].w));
        }
        zzs[tid] = zz;
        unsigned p[32];
#pragma unroll
        for (int i = 0; i < 16; ++i) {
            __nv_bfloat162 b0 = __float22bfloat162_rn(make_float2(-2.f * v[i].x, -2.f * v[i].y));
            __nv_bfloat162 b1 = __float22bfloat162_rn(make_float2(-2.f * v[i].z, -2.f * v[i].w));
            p[2 * i] = *(unsigned*)&b0;
            p[2 * i + 1] = *(unsigned*)&b1;
        }
        uint4* d4 = (uint4*)(zbw + tid * 36);
#pragma unroll
        for (int i = 0; i < 8; ++i) d4[i] = make_uint4(p[4 * i], p[4 * i + 1], p[4 * i + 2], p[4 * i + 3]);
    } else {
        int t2 = tid - ROWS_CTA;                       // 0..383
        const uint4* src = (const uint4*)g_cbw;
        for (int u = t2; u < Kc * 8; u += THREADS - ROWS_CTA) {
            int r = u >> 3, c4 = u & 7;
            *(uint4*)(bsw + r * 40 + c4 * 4) = src[u];
        }
    }
    __syncthreads();

    // ---------------- A fragments: rows ra, ra+8 ----------------
    const int ra = gidx * 16 + rg;
    unsigned a[16];
#pragma unroll
    for (int ks = 0; ks < 4; ++ks) {
        int rbase = ra * 36;
        a[ks * 4 + 0] = zbw[rbase + q + ks * 8];
        a[ks * 4 + 1] = zbw[rbase + 8 * 36 + q + ks * 8];
        a[ks * 4 + 2] = zbw[rbase + q + 4 + ks * 8];
        a[ks * 4 + 3] = zbw[rbase + 8 * 36 + q + 4 + ks * 8];
    }

    // ---------------- pass 1: 32 tiles, scores cached in registers ----------------
    const int toff = th * 32;
    float mr0 = 1e30f, mr1 = 1e30f;
    unsigned sc[64];
#pragma unroll
    for (int i = 0; i < 32; ++i) {
        int t = toff + i;
        const unsigned* bp = bsw + (t * 8 + rg) * 40 + 2 * q;
        uint2 b0 = *(const uint2*)(bp);
        uint2 b1 = *(const uint2*)(bp + 8);
        uint2 b2 = *(const uint2*)(bp + 16);
        uint2 b3 = *(const uint2*)(bp + 24);
        float d0 = 0.f, d1 = 0.f, d2 = 0.f, d3 = 0.f;
        float f0 = 0.f, f1 = 0.f, f2 = 0.f, f3 = 0.f;
        mma16816(d0, d1, d2, d3, a[0], a[1], a[2], a[3], b0.x, b0.y);
        mma16816(d0, d1, d2, d3, a[4], a[5], a[6], a[7], b1.x, b1.y);
        mma16816(f0, f1, f2, f3, a[8], a[9], a[10], a[11], b2.x, b2.y);
        mma16816(f0, f1, f2, f3, a[12], a[13], a[14], a[15], b3.x, b3.y);
        float c0 = d0 + f0, c1 = d1 + f1, c2 = d2 + f2, c3 = d3 + f3;
        mr0 = fminf(mr0, fminf(c0, c1));
        mr1 = fminf(mr1, fminf(c2, c3));
        __nv_bfloat162 p0 = __float22bfloat162_rn(make_float2(c0, c1));
        __nv_bfloat162 p1 = __float22bfloat162_rn(make_float2(c2, c3));
        sc[2 * i] = *(unsigned*)&p0;
        sc[2 * i + 1] = *(unsigned*)&p1;
    }

    // quad reduce + cross-half exchange
#pragma unroll
    for (int off = 1; off < 4; off <<= 1) {
        mr0 = fminf(mr0, __shfl_xor_sync(0xffffffffu, mr0, off));
        mr1 = fminf(mr1, __shfl_xor_sync(0xffffffffu, mr1, off));
    }
    if (q == 0) {
        mrex[th * 128 + ra] = mr0;
        mrex[th * 128 + ra + 8] = mr1;
    }
    __syncthreads();
    const float marginFast = MARGIN + SSLACK + __int_as_float(g_eemax_i);
    const float t0 = fminf(mr0, mrex[(1 - th) * 128 + ra]) + marginFast;
    const float t1 = fminf(mr1, mrex[(1 - th) * 128 + ra + 8]) + marginFast;

    // ---------------- pass 2: register scan, enqueue candidates ----------------
#define PUSH(rowv, jv) do {                                                       \
        unsigned pk_ = (unsigned)(rowv) | ((unsigned)(jv) << 7);                  \
        int qi_ = atomicAdd(qcnt + wid, 1);                                       \
        if (qi_ < QCAP) que[wid * QCAP + qi_] = pk_;                              \
        else exact_commit(pk_, z, cb, blockRow, zzs, minr);                       \
    } while (0)

#pragma unroll
    for (int i = 0; i < 32; ++i) {
        __nv_bfloat162 p0 = *(__nv_bfloat162*)&sc[2 * i];
        __nv_bfloat162 p1 = *(__nv_bfloat162*)&sc[2 * i + 1];
        float c0 = __bfloat162float(__low2bfloat16(p0));
        float c1 = __bfloat162float(__high2bfloat16(p0));
        float c2 = __bfloat162float(__low2bfloat16(p1));
        float c3 = __bfloat162float(__high2bfloat16(p1));
        int jb = (toff + i) * 8 + 2 * q;
        if (c0 <= t0) PUSH(ra, jb);
        if (c1 <= t0) PUSH(ra, jb + 1);
        if (c2 <= t1) PUSH(ra + 8, jb);
        if (c3 <= t1) PUSH(ra + 8, jb + 1);
    }
#undef PUSH

    // ---------------- drain: 32 lanes rescore distinct candidates ----------------
    __syncwarp();
    int n = *(volatile int*)(qcnt + wid);
    if (n > QCAP) n = QCAP;
    for (int base = 0; base < n; base += 32) {
        int k2 = base + lane;
        if (k2 < n) exact_commit(que[wid * QCAP + k2], z, cb, blockRow, zzs, minr);
    }
    __syncthreads();

    // ---------------- gather + write both tuple halves ----------------
    {
        int row = tid >> 2, seg = tid & 3;
        int j = (int)(unsigned)(minr[row] & 0xFFFFFFFFull);
        size_t g = blockRow + row;
        const float4* s4 = (const float4*)(cb + (size_t)j * Dm + seg * 16);
        float4* o1 = (float4*)(out + g * Dm + seg * 16);
        float4* o2 = (half > 0) ? (float4*)(out + half + g * Dm + seg * 16) : nullptr;
#pragma unroll
        for (int i = 0; i < 4; ++i) {
            float4 tv = s4[i];
            o1[i] = tv;
            if (o2) o2[i] = tv;
        }
    }
}

extern "C" void kernel_launch(void* const* d_in, const int* in_sizes, int n_in,
                              void* d_out, int out_size) {
    const float* z = (const float*)d_in[0];
    const float* cb = (const float*)d_in[1];
    float* out = (float*)d_out;
    const int N = in_sizes[0] / Dm;                      // 131072
    long long half = ((long long)out_size >= 2LL * N * Dm) ? (long long)out_size / 2 : 0;

    cudaFuncSetAttribute(vq_kernel, cudaFuncAttributeMaxDynamicSharedMemorySize, SM_TOTAL);
    prep_kernel<<<2, 256>>>(cb);
    vq_kernel<<<N / ROWS_CTA, THREADS, SM_TOTAL>>>(z, cb, out, half);
}

// round 9
// speedup vs baseline: 1.0427x; 1.0427x over previous
#include <cuda_runtime.h>
#include <cuda_bf16.h>
#include <cstdint>

// VQVAE nearest-codebook: single-pass bf16 mma.sync fast scores with streaming
// provisional-threshold candidate push + warp-parallel exact fp32 rescore.
// z:[131072,64] f32, cb:[512,64] f32. out = (gather, gather).

#define Dm 64
#define Kc 512
#define ROWS_CTA 512
#define THREADS 512
#define MARGIN 2e-3f
#define QCAP 256

__device__ float g_ee[Kc];            // exact sequential ||e_j||^2
__device__ int g_eemax_i = 0;         // max ee (float bits)
__device__ unsigned g_cbw[Kc * 32];   // codebook rows, bf16x2 words, B-pair permuted

// ---- smem layout (bytes) ----
#define SM_ZBW  0                      // 512 x 36 u32 bf16x2(-2z)                73728
#define SM_BSW  73728                  // 512 x 40 u32 codebook (pitch 40)        81920
#define SM_ZZS  155648                 // 512 f32 exact zz                         2048
#define SM_MINR 157696                 // 512 u64 (score_bits<<32 | j)             4096
#define SM_QCNT 161792                 // 16 i32 (+pad)                             128
#define SM_QUE  161920                 // 16 x 256 u32 candidates                 16384
#define SM_TOTAL 178304

__global__ void prep_kernel(const float* __restrict__ cb) {
    int j = blockIdx.x * blockDim.x + threadIdx.x;
    if (j < Kc) {
        const float* e = cb + j * Dm;
        float s = 0.0f;
#pragma unroll
        for (int k = 0; k < Dm; ++k) s = __fadd_rn(s, __fmul_rn(e[k], e[k]));
        g_ee[j] = s;
        atomicMax(&g_eemax_i, __float_as_int(s));   // s >= 0: int order == float order
        // permuted: position p holds word w = (p&~7) + ((p>>1)&3) + 4*(p&1)
#pragma unroll
        for (int p = 0; p < 32; ++p) {
            int w = (p & ~7) + ((p >> 1) & 3) + 4 * (p & 1);
            __nv_bfloat162 b = __float22bfloat162_rn(make_float2(e[2 * w], e[2 * w + 1]));
            g_cbw[j * 32 + p] = *(unsigned*)&b;
        }
    }
}

__device__ __forceinline__ void mma16816(float& c0, float& c1, float& c2, float& c3,
                                         unsigned a0, unsigned a1, unsigned a2, unsigned a3,
                                         unsigned b0, unsigned b1) {
    asm volatile("mma.sync.aligned.m16n8k16.row.col.f32.bf16.bf16.f32 "
                 "{%0,%1,%2,%3},{%4,%5,%6,%7},{%8,%9},{%0,%1,%2,%3};"
                 : "+f"(c0), "+f"(c1), "+f"(c2), "+f"(c3)
                 : "r"(a0), "r"(a1), "r"(a2), "r"(a3), "r"(b0), "r"(b1));
}

// Exact rescore (sequential fp32, reference rounding) + 64-bit atomicMin commit.
// key=(score_bits<<32)|j: scores >= 0 so bit order == value order; ties -> min j.
__device__ __noinline__ void exact_commit(unsigned pk, const float* __restrict__ z,
                                          const float* __restrict__ cb, size_t blockRow,
                                          const float* zzs, unsigned long long* minr) {
    int row = pk & 511;
    int j = pk >> 9;
    const float4* zp = (const float4*)(z + (blockRow + row) * Dm);
    const float4* ep = (const float4*)(cb + (size_t)j * Dm);
    float dot = 0.0f;
#pragma unroll
    for (int i = 0; i < 16; ++i) {
        float4 a = __ldg(zp + i);
        float4 b = __ldg(ep + i);
        dot = __fmaf_rn(a.x, b.x, dot);
        dot = __fmaf_rn(a.y, b.y, dot);
        dot = __fmaf_rn(a.z, b.z, dot);
        dot = __fmaf_rn(a.w, b.w, dot);
    }
    float sx = __fadd_rn(__fadd_rn(zzs[row], g_ee[j]), __fmul_rn(-2.0f, dot));
    unsigned long long key = ((unsigned long long)__float_as_uint(sx) << 32) | (unsigned)j;
    atomicMin(minr + row, key);
}

__global__ void __launch_bounds__(THREADS, 1)
vq_kernel(const float* __restrict__ z, const float* __restrict__ cb,
          float* __restrict__ out, long long half) {
    extern __shared__ char sm[];
    unsigned* zbw = (unsigned*)(sm + SM_ZBW);
    unsigned* bsw = (unsigned*)(sm + SM_BSW);
    float* zzs = (float*)(sm + SM_ZZS);
    unsigned long long* minr = (unsigned long long*)(sm + SM_MINR);
    int* qcnt = (int*)(sm + SM_QCNT);
    unsigned* que = (unsigned*)(sm + SM_QUE);

    const int tid = threadIdx.x, lane = tid & 31, wid = tid >> 5;
    const int q = lane & 3, rg = lane >> 2;
    const size_t blockRow = (size_t)blockIdx.x * ROWS_CTA;

    if (tid < 16) qcnt[tid] = 0;
    minr[tid] = ~0ull;

    // ---------------- prolog: z rows + exact zz + bf16(-2z) ----------------
    {
        const float4* zr = (const float4*)(z + (blockRow + tid) * Dm);
        float4 v[16];
#pragma unroll
        for (int i = 0; i < 16; ++i) v[i] = zr[i];
        float zz = 0.0f;
#pragma unroll
        for (int i = 0; i < 16; ++i) {
            zz = __fadd_rn(zz, __fmul_rn(v[i].x, v[i].x));
            zz = __fadd_rn(zz, __fmul_rn(v[i].y, v[i].y));
            zz = __fadd_rn(zz, __fmul_rn(v[i].z, v[i].z));
            zz = __fadd_rn(zz, __fmul_rn(v[i].w, v[i].w));
        }
        zzs[tid] = zz;
        unsigned p[32];
#pragma unroll
        for (int i = 0; i < 16; ++i) {
            __nv_bfloat162 b0 = __float22bfloat162_rn(make_float2(-2.f * v[i].x, -2.f * v[i].y));
            __nv_bfloat162 b1 = __float22bfloat162_rn(make_float2(-2.f * v[i].z, -2.f * v[i].w));
            p[2 * i] = *(unsigned*)&b0;
            p[2 * i + 1] = *(unsigned*)&b1;
        }
        uint4* d4 = (uint4*)(zbw + tid * 36);
#pragma unroll
        for (int i = 0; i < 8; ++i) d4[i] = make_uint4(p[4 * i], p[4 * i + 1], p[4 * i + 2], p[4 * i + 3]);
    }
    // codebook bf16x2 words -> pitch-40 smem (vectorized, coalesced)
    {
        const uint4* src = (const uint4*)g_cbw;
#pragma unroll
        for (int it = 0; it < 8; ++it) {
            int u = tid + it * THREADS;          // 0..4095 uint4 chunks
            int r = u >> 3, c4 = u & 7;
            *(uint4*)(bsw + r * 40 + c4 * 4) = src[u];
        }
    }
    __syncthreads();

    // ---------------- A fragments: M=32 (rows ra, ra+8, ra+16, ra+24) ----------------
    const int ra = wid * 32 + rg;
    unsigned a[32];
#pragma unroll
    for (int b = 0; b < 2; ++b)
#pragma unroll
        for (int ks = 0; ks < 4; ++ks) {
            int rbase = (ra + 16 * b) * 36;
            a[b * 16 + ks * 4 + 0] = zbw[rbase + q + ks * 8];
            a[b * 16 + ks * 4 + 1] = zbw[rbase + 8 * 36 + q + ks * 8];
            a[b * 16 + ks * 4 + 2] = zbw[rbase + q + 4 + ks * 8];
            a[b * 16 + ks * 4 + 3] = zbw[rbase + 8 * 36 + q + 4 + ks * 8];
        }

    const float marginFast = MARGIN + __int_as_float(g_eemax_i);

    // ---------------- single pass: score, stream thresholds, push ----------------
    float m0 = 1e30f, m1 = 1e30f, m2 = 1e30f, m3 = 1e30f;   // running lane row-mins

#define PUSH(rowv, jv) do {                                                       \
        unsigned pk_ = (unsigned)(rowv) | ((unsigned)(jv) << 9);                  \
        int qi_ = atomicAdd(qcnt + wid, 1);                                       \
        if (qi_ < QCAP) que[wid * QCAP + qi_] = pk_;                              \
        else exact_commit(pk_, z, cb, blockRow, zzs, minr);                       \
    } while (0)

#pragma unroll 1
    for (int ch = 0; ch < 16; ++ch) {
        float cc[32];
        // -- score 4 tiles, update running mins --
#pragma unroll
        for (int tt = 0; tt < 4; ++tt) {
            int t = ch * 4 + tt;
            const unsigned* bp = bsw + (t * 8 + rg) * 40 + 2 * q;
            uint2 b0 = *(const uint2*)(bp);
            uint2 b1 = *(const uint2*)(bp + 8);
            uint2 b2 = *(const uint2*)(bp + 16);
            uint2 b3 = *(const uint2*)(bp + 24);
            float c0 = 0.f, c1 = 0.f, c2 = 0.f, c3 = 0.f;
            float c4 = 0.f, c5 = 0.f, c6 = 0.f, c7 = 0.f;
            mma16816(c0, c1, c2, c3, a[0], a[1], a[2], a[3], b0.x, b0.y);
            mma16816(c0, c1, c2, c3, a[4], a[5], a[6], a[7], b1.x, b1.y);
            mma16816(c0, c1, c2, c3, a[8], a[9], a[10], a[11], b2.x, b2.y);
            mma16816(c0, c1, c2, c3, a[12], a[13], a[14], a[15], b3.x, b3.y);
            mma16816(c4, c5, c6, c7, a[16], a[17], a[18], a[19], b0.x, b0.y);
            mma16816(c4, c5, c6, c7, a[20], a[21], a[22], a[23], b1.x, b1.y);
            mma16816(c4, c5, c6, c7, a[24], a[25], a[26], a[27], b2.x, b2.y);
            mma16816(c4, c5, c6, c7, a[28], a[29], a[30], a[31], b3.x, b3.y);
            m0 = fminf(m0, fminf(c0, c1));
            m1 = fminf(m1, fminf(c2, c3));
            m2 = fminf(m2, fminf(c4, c5));
            m3 = fminf(m3, fminf(c6, c7));
            cc[tt * 8 + 0] = c0; cc[tt * 8 + 1] = c1; cc[tt * 8 + 2] = c2; cc[tt * 8 + 3] = c3;
            cc[tt * 8 + 4] = c4; cc[tt * 8 + 5] = c5; cc[tt * 8 + 6] = c6; cc[tt * 8 + 7] = c7;
        }
        // -- provisional thresholds from quad-reduced running mins --
        float r0 = m0, r1 = m1, r2 = m2, r3 = m3;
#pragma unroll
        for (int off = 1; off < 4; off <<= 1) {
            r0 = fminf(r0, __shfl_xor_sync(0xffffffffu, r0, off));
            r1 = fminf(r1, __shfl_xor_sync(0xffffffffu, r1, off));
            r2 = fminf(r2, __shfl_xor_sync(0xffffffffu, r2, off));
            r3 = fminf(r3, __shfl_xor_sync(0xffffffffu, r3, off));
        }
        const float t0 = r0 + marginFast, t1 = r1 + marginFast;
        const float t2 = r2 + marginFast, t3 = r3 + marginFast;
        const float thrmax = fmaxf(fmaxf(t0, t1), fmaxf(t2, t3));
        // -- push candidates from this chunk (window only ever shrinks later) --
#pragma unroll
        for (int tt = 0; tt < 4; ++tt) {
            const float* c = cc + tt * 8;
            float tmin = fminf(fminf(fminf(c[0], c[1]), fminf(c[2], c[3])),
                               fminf(fminf(c[4], c[5]), fminf(c[6], c[7])));
            if (tmin <= thrmax) {
                int jb = (ch * 4 + tt) * 8 + 2 * q;
                if (c[0] <= t0) PUSH(ra, jb);
                if (c[1] <= t0) PUSH(ra, jb + 1);
                if (c[2] <= t1) PUSH(ra + 8, jb);
                if (c[3] <= t1) PUSH(ra + 8, jb + 1);
                if (c[4] <= t2) PUSH(ra + 16, jb);
                if (c[5] <= t2) PUSH(ra + 16, jb + 1);
                if (c[6] <= t3) PUSH(ra + 24, jb);
                if (c[7] <= t3) PUSH(ra + 24, jb + 1);
            }
        }
    }
#undef PUSH

    // ---------------- drain: 32 lanes rescore distinct candidates ----------------
    __syncwarp();
    int n = *(volatile int*)(qcnt + wid);
    if (n > QCAP) n = QCAP;
    for (int base = 0; base < n; base += 32) {
        int k2 = base + lane;
        if (k2 < n) exact_commit(que[wid * QCAP + k2], z, cb, blockRow, zzs, minr);
    }
    __syncthreads();

    // ---------------- gather + write both tuple halves ----------------
    {
        int j = (int)(unsigned)(minr[tid] & 0xFFFFFFFFull);
        size_t g = blockRow + tid;
        const float4* s4 = (const float4*)(cb + (size_t)j * Dm);
        float4* o1 = (float4*)(out + g * Dm);
        float4* o2 = (half > 0) ? (float4*)(out + half + g * Dm) : nullptr;
#pragma unroll
        for (int i = 0; i < 16; ++i) {
            float4 tv = s4[i];
            o1[i] = tv;
            if (o2) o2[i] = tv;
        }
    }
}

extern "C" void kernel_launch(void* const* d_in, const int* in_sizes, int n_in,
                              void* d_out, int out_size) {
    const float* z = (const float*)d_in[0];
    const float* cb = (const float*)d_in[1];
    float* out = (float*)d_out;
    const int N = in_sizes[0] / Dm;                      // 131072
    long long half = ((long long)out_size >= 2LL * N * Dm) ? (long long)out_size / 2 : 0;

    cudaFuncSetAttribute(vq_kernel, cudaFuncAttributeMaxDynamicSharedMemorySize, SM_TOTAL);
    prep_kernel<<<2, 256>>>(cb);
    vq_kernel<<<N / ROWS_CTA, THREADS, SM_TOTAL>>>(z, cb, out, half);
}